// round 2
// baseline (speedup 1.0000x reference)
#include <cuda_runtime.h>

// ProbsNet fused single-kernel:
//   out = sum_i c0[i]*tmp0[i] + c1[i]*tmp1[i]
//   tmpX[i] = sum_d sigmoid(pB*(pBEV*BEV + STX[i,d])) * WX[i,d]
//   c0 = calc_probs(probs0)/5 ; c1 = sum(calc_probs(probs1..4))/5
// 176 MB fp32 streaming -> HBM-bound; everything else folded in.

#define D        131072
#define NROWS    84
#define VPR      (D / 4)            // 32768 float4 per row
#define NVEC     (NROWS * VPR)      // 2752512 float4 per (ST,W) pair
#define GRID     2368               // 148 SMs * 16 blocks
#define BLOCK    256

__device__ float        g_part[GRID];
__device__ unsigned int g_sem = 0;   // self-resetting semaphore (graph-replay safe)

// Compute entry e (0..83) of calc_probs(logits): flattened (4,21) layout
//   row i: [p_i, then for j: p_i*p_j, p_i*p_j*p_0..p_3]
__device__ __forceinline__ float probs_entry(const float* __restrict__ logits, int e) {
    float e0 = __expf(logits[0]);
    float e1 = __expf(logits[1]);
    float e2 = __expf(logits[2]);
    float e3 = __expf(logits[3]);
    float inv = __fdividef(1.0f, e0 + e1 + e2 + e3);
    float p[4] = {e0 * inv, e1 * inv, e2 * inv, e3 * inv};

    int i = e / 21;
    int r = e - i * 21;
    float v = p[i];
    if (r > 0) {
        int q  = r - 1;
        int j  = q / 5;
        int rr = q - j * 5;
        v *= p[j];
        if (rr > 0) v *= p[rr - 1];
    }
    return v;
}

__global__ void __launch_bounds__(BLOCK)
fused_kernel(const float* __restrict__ BEV,
             const float* __restrict__ ST0, const float* __restrict__ W0,
             const float* __restrict__ ST1, const float* __restrict__ W1,
             const float* __restrict__ probs0, const float* __restrict__ probs1,
             const float* __restrict__ probs2, const float* __restrict__ probs3,
             const float* __restrict__ probs4,
             const float* __restrict__ pBEV, const float* __restrict__ pB,
             float* __restrict__ out) {
    __shared__ float sc[2 * NROWS];
    const int tid = threadIdx.x;

    // --- per-block coefficient table (redundant across blocks, ~300 cyc) ---
    if (tid < NROWS) {
        sc[tid] = 0.2f * probs_entry(probs0, tid);
        float c1 = probs_entry(probs1, tid) + probs_entry(probs2, tid)
                 + probs_entry(probs3, tid) + probs_entry(probs4, tid);
        sc[NROWS + tid] = 0.2f * c1;
    }
    __syncthreads();

    const float bev   = pBEV[0] * BEV[0];
    const float scale = pB[0];

    const float4* __restrict__ st0 = (const float4*)ST0;
    const float4* __restrict__ w0  = (const float4*)W0;
    const float4* __restrict__ st1 = (const float4*)ST1;
    const float4* __restrict__ w1  = (const float4*)W1;

    const int stride = GRID * BLOCK;
    float acc = 0.0f;

    // --- stream pair 0 ---
    for (int v = blockIdx.x * BLOCK + tid; v < NVEC; v += stride) {
        float4 s4 = st0[v];
        float4 w4 = w0[v];
        float  c  = sc[v >> 15];                       // v / VPR
        float t;
        t  = w4.x * __fdividef(1.0f, 1.0f + __expf(-scale * (bev + s4.x)));
        t += w4.y * __fdividef(1.0f, 1.0f + __expf(-scale * (bev + s4.y)));
        t += w4.z * __fdividef(1.0f, 1.0f + __expf(-scale * (bev + s4.z)));
        t += w4.w * __fdividef(1.0f, 1.0f + __expf(-scale * (bev + s4.w)));
        acc = fmaf(c, t, acc);
    }
    // --- stream pair 1 ---
    for (int v = blockIdx.x * BLOCK + tid; v < NVEC; v += stride) {
        float4 s4 = st1[v];
        float4 w4 = w1[v];
        float  c  = sc[NROWS + (v >> 15)];
        float t;
        t  = w4.x * __fdividef(1.0f, 1.0f + __expf(-scale * (bev + s4.x)));
        t += w4.y * __fdividef(1.0f, 1.0f + __expf(-scale * (bev + s4.y)));
        t += w4.z * __fdividef(1.0f, 1.0f + __expf(-scale * (bev + s4.z)));
        t += w4.w * __fdividef(1.0f, 1.0f + __expf(-scale * (bev + s4.w)));
        acc = fmaf(c, t, acc);
    }

    // --- block reduce (fixed tree, deterministic) ---
    for (int off = 16; off > 0; off >>= 1)
        acc += __shfl_down_sync(0xFFFFFFFFu, acc, off);

    __shared__ float sm[BLOCK / 32];
    int lane = tid & 31;
    int wid  = tid >> 5;
    if (lane == 0) sm[wid] = acc;
    __syncthreads();
    if (wid == 0) {
        float b = (lane < BLOCK / 32) ? sm[lane] : 0.0f;
        for (int off = 4; off > 0; off >>= 1)
            b += __shfl_down_sync(0xFFFFFFFFu, b, off);
        if (lane == 0) g_part[blockIdx.x] = b;
    }

    // --- last block folds the partials (deterministic fixed-order sum) ---
    __shared__ bool is_last;
    __threadfence();
    if (tid == 0)
        is_last = (atomicAdd(&g_sem, 1u) == GRID - 1);
    __syncthreads();

    if (is_last) {
        __threadfence();
        float a2 = 0.0f;
        for (int i = tid; i < GRID; i += BLOCK)
            a2 += g_part[i];
        for (int off = 16; off > 0; off >>= 1)
            a2 += __shfl_down_sync(0xFFFFFFFFu, a2, off);
        if (lane == 0) sm[wid] = a2;
        __syncthreads();
        if (tid == 0) {
            float s = 0.0f;
            #pragma unroll
            for (int i = 0; i < BLOCK / 32; i++) s += sm[i];
            out[0] = s;
            g_sem  = 0;   // reset for next graph replay
        }
    }
}

// Input order (metadata): BEV, ST0, Weight0, ST1, Weight1, Problem,
// probs0..probs4, pBEV, pB
extern "C" void kernel_launch(void* const* d_in, const int* in_sizes, int n_in,
                              void* d_out, int out_size) {
    const float* BEV    = (const float*)d_in[0];
    const float* ST0    = (const float*)d_in[1];
    const float* W0     = (const float*)d_in[2];
    const float* ST1    = (const float*)d_in[3];
    const float* W1     = (const float*)d_in[4];
    const float* probs0 = (const float*)d_in[6];
    const float* probs1 = (const float*)d_in[7];
    const float* probs2 = (const float*)d_in[8];
    const float* probs3 = (const float*)d_in[9];
    const float* probs4 = (const float*)d_in[10];
    const float* pBEV   = (const float*)d_in[11];
    const float* pB     = (const float*)d_in[12];

    fused_kernel<<<GRID, BLOCK>>>(BEV, ST0, W0, ST1, W1,
                                  probs0, probs1, probs2, probs3, probs4,
                                  pBEV, pB, (float*)d_out);
}

// round 3
// speedup vs baseline: 1.0976x; 1.0976x over previous
#include <cuda_runtime.h>

// ProbsNet fused single-kernel, tile-blocked for MLP:
//   out = sum_i c0[i]*tmp0[i] + c1[i]*tmp1[i]
//   tmpX[i] = sum_d sigmoid(pB*(pBEV*BEV + STX[i,d])) * WX[i,d]
// 176 MB fp32 streaming -> HBM-bound. Tiles of 1024 float4 never straddle a
// row (32768 float4/row), so coefficient is scalar per tile.

#define D        131072
#define NROWS    84
#define VPR      (D / 4)              // 32768 float4 per row
#define NVEC     (NROWS * VPR)        // 2752512 float4 per (ST,W) pair
#define BLOCK    256
#define UNROLL   4
#define TILE     (BLOCK * UNROLL)     // 1024 float4 per tile
#define TILES1   (NVEC / TILE)        // 2688 tiles per pair (exact)
#define TILES    (2 * TILES1)         // 5376
#define GRID     1184                 // 148 SMs * 8 blocks = exactly resident

__device__ float        g_part[GRID];
__device__ unsigned int g_sem = 0;    // self-resetting (graph-replay safe)

// Entry e (0..83) of calc_probs(logits), flattened (4,21) layout.
__device__ __forceinline__ float probs_entry(const float* __restrict__ logits, int e) {
    float e0 = __expf(logits[0]);
    float e1 = __expf(logits[1]);
    float e2 = __expf(logits[2]);
    float e3 = __expf(logits[3]);
    float inv = __fdividef(1.0f, e0 + e1 + e2 + e3);
    float p[4] = {e0 * inv, e1 * inv, e2 * inv, e3 * inv};
    int i = e / 21;
    int r = e - i * 21;
    float v = p[i];
    if (r > 0) {
        int q  = r - 1;
        int j  = q / 5;
        int rr = q - j * 5;
        v *= p[j];
        if (rr > 0) v *= p[rr - 1];
    }
    return v;
}

__device__ __forceinline__ float sig_dot4(float4 s4, float4 w4, float scale, float bev) {
    float t;
    t  = w4.x * __fdividef(1.0f, 1.0f + __expf(-scale * (bev + s4.x)));
    t += w4.y * __fdividef(1.0f, 1.0f + __expf(-scale * (bev + s4.y)));
    t += w4.z * __fdividef(1.0f, 1.0f + __expf(-scale * (bev + s4.z)));
    t += w4.w * __fdividef(1.0f, 1.0f + __expf(-scale * (bev + s4.w)));
    return t;
}

__global__ void __launch_bounds__(BLOCK)
fused_kernel(const float* __restrict__ BEV,
             const float* __restrict__ ST0, const float* __restrict__ W0,
             const float* __restrict__ ST1, const float* __restrict__ W1,
             const float* __restrict__ probs0, const float* __restrict__ probs1,
             const float* __restrict__ probs2, const float* __restrict__ probs3,
             const float* __restrict__ probs4,
             const float* __restrict__ pBEV, const float* __restrict__ pB,
             float* __restrict__ out) {
    __shared__ float sc[2 * NROWS];
    const int tid = threadIdx.x;

    if (tid < NROWS) {
        sc[tid] = 0.2f * probs_entry(probs0, tid);
        float c1 = probs_entry(probs1, tid) + probs_entry(probs2, tid)
                 + probs_entry(probs3, tid) + probs_entry(probs4, tid);
        sc[NROWS + tid] = 0.2f * c1;
    }
    __syncthreads();

    const float bev   = pBEV[0] * BEV[0];
    const float scale = pB[0];

    const float4* __restrict__ st0 = (const float4*)ST0;
    const float4* __restrict__ w0  = (const float4*)W0;
    const float4* __restrict__ st1 = (const float4*)ST1;
    const float4* __restrict__ w1  = (const float4*)W1;

    float acc = 0.0f;

    // Persistent grid-stride over tiles. One coefficient per tile.
    for (int t = blockIdx.x; t < TILES; t += GRID) {
        const bool second = (t >= TILES1);
        const int  tt     = second ? (t - TILES1) : t;
        const int  v0     = tt * TILE;
        const float4* __restrict__ st = second ? st1 : st0;
        const float4* __restrict__ w  = second ? w1  : w0;
        const float c = sc[(second ? NROWS : 0) + (v0 >> 15)];

        // 8 front-batched LDG.128 (4 st + 4 w), all independent.
        float4 s[UNROLL], ww[UNROLL];
        #pragma unroll
        for (int u = 0; u < UNROLL; u++) {
            int v = v0 + u * BLOCK + tid;
            s[u]  = st[v];
            ww[u] = w[v];
        }

        float tsum = 0.0f;
        #pragma unroll
        for (int u = 0; u < UNROLL; u++)
            tsum += sig_dot4(s[u], ww[u], scale, bev);

        acc = fmaf(c, tsum, acc);
    }

    // --- block reduce (fixed tree, deterministic) ---
    for (int off = 16; off > 0; off >>= 1)
        acc += __shfl_down_sync(0xFFFFFFFFu, acc, off);

    __shared__ float sm[BLOCK / 32];
    int lane = tid & 31;
    int wid  = tid >> 5;
    if (lane == 0) sm[wid] = acc;
    __syncthreads();
    if (wid == 0) {
        float b = (lane < BLOCK / 32) ? sm[lane] : 0.0f;
        for (int off = 4; off > 0; off >>= 1)
            b += __shfl_down_sync(0xFFFFFFFFu, b, off);
        if (lane == 0) g_part[blockIdx.x] = b;
    }

    // --- last block folds partials (deterministic fixed-order) ---
    __shared__ bool is_last;
    __threadfence();
    if (tid == 0)
        is_last = (atomicAdd(&g_sem, 1u) == GRID - 1);
    __syncthreads();

    if (is_last) {
        __threadfence();
        float a2 = 0.0f;
        for (int i = tid; i < GRID; i += BLOCK)
            a2 += g_part[i];
        for (int off = 16; off > 0; off >>= 1)
            a2 += __shfl_down_sync(0xFFFFFFFFu, a2, off);
        if (lane == 0) sm[wid] = a2;
        __syncthreads();
        if (tid == 0) {
            float s = 0.0f;
            #pragma unroll
            for (int i = 0; i < BLOCK / 32; i++) s += sm[i];
            out[0] = s;
            g_sem  = 0;
        }
    }
}

// Input order: BEV, ST0, Weight0, ST1, Weight1, Problem, probs0..4, pBEV, pB
extern "C" void kernel_launch(void* const* d_in, const int* in_sizes, int n_in,
                              void* d_out, int out_size) {
    const float* BEV    = (const float*)d_in[0];
    const float* ST0    = (const float*)d_in[1];
    const float* W0     = (const float*)d_in[2];
    const float* ST1    = (const float*)d_in[3];
    const float* W1     = (const float*)d_in[4];
    const float* probs0 = (const float*)d_in[6];
    const float* probs1 = (const float*)d_in[7];
    const float* probs2 = (const float*)d_in[8];
    const float* probs3 = (const float*)d_in[9];
    const float* probs4 = (const float*)d_in[10];
    const float* pBEV   = (const float*)d_in[11];
    const float* pB     = (const float*)d_in[12];

    fused_kernel<<<GRID, BLOCK>>>(BEV, ST0, W0, ST1, W1,
                                  probs0, probs1, probs2, probs3, probs4,
                                  pBEV, pB, (float*)d_out);
}